// round 11
// baseline (speedup 1.0000x reference)
#include <cuda_runtime.h>
#include <cuda_bf16.h>
#include <stdint.h>

#define BATCH 32
#define CH    256
#define NPIX  1024
#define GROUPS 8
#define CPG   32
#define EPSV  1e-5f

#define BKC 64
#define TILE_B  16384
#define STAGE_B (2 * TILE_B)
#define NSG 3
#define SMEM_REQ (NSG * STAGE_B)     // 98304 for gemm kernels
#define FA_SMEM 98304                // 96KB: Q/out 32K + K/Wp 32K + V/Wp 32K
#define HT_STRIDE 1042
#define GNHT_SMEM (CPG * HT_STRIDE * 2)

typedef __nv_bfloat16 bf16;

// ---- scratch ----
__device__ bf16 g_hT [(size_t)BATCH * NPIX * CH];
__device__ bf16 g_qT [(size_t)BATCH * NPIX * CH];    // [b][n][c] (W_q pre-scaled log2e/16)
__device__ bf16 g_kT [(size_t)BATCH * NPIX * CH];    // [b][m][c]
__device__ bf16 g_v  [(size_t)BATCH * CH * NPIX];    // [b][c][m]
__device__ bf16 g_wqk[(size_t)512 * CH];
__device__ bf16 g_wv [(size_t)CH * CH];
__device__ bf16 g_wp [(size_t)CH * CH];

// ================= helpers =================
__device__ __forceinline__ uint32_t smem_u32(const void* p) {
    uint32_t a;
    asm("{ .reg .u64 t; cvta.to.shared.u64 t, %1; cvt.u32.u64 %0, t; }" : "=r"(a) : "l"(p));
    return a;
}
__device__ __forceinline__ void cpa16(uint32_t d, const void* s) {
    asm volatile("cp.async.cg.shared.global [%0], [%1], 16;" :: "r"(d), "l"(s));
}
__device__ __forceinline__ uint32_t pk2(float lo, float hi) {
    uint32_t r;
    asm("cvt.rn.bf16x2.f32 %0, %1, %2;" : "=r"(r) : "f"(hi), "f"(lo));
    return r;
}
__device__ __forceinline__ void mma_bf16(float c[4], const uint32_t a[4], uint32_t b0, uint32_t b1) {
    asm volatile("mma.sync.aligned.m16n8k16.row.col.f32.bf16.bf16.f32 "
                 "{%0,%1,%2,%3}, {%4,%5,%6,%7}, {%8,%9}, {%0,%1,%2,%3};\n"
                 : "+f"(c[0]), "+f"(c[1]), "+f"(c[2]), "+f"(c[3])
                 : "r"(a[0]), "r"(a[1]), "r"(a[2]), "r"(a[3]), "r"(b0), "r"(b1));
}
__device__ __forceinline__ void ldmx4(uint32_t r[4], uint32_t addr) {
    asm volatile("ldmatrix.sync.aligned.m8n8.x4.shared.b16 {%0,%1,%2,%3}, [%4];"
                 : "=r"(r[0]), "=r"(r[1]), "=r"(r[2]), "=r"(r[3]) : "r"(addr));
}
__device__ __forceinline__ void sts32(uint32_t addr, uint32_t v) {
    asm volatile("st.shared.b32 [%0], %1;" :: "r"(addr), "r"(v));
}
// 128B-row swizzle: row r, 16B chunk kc in [0,8)
__device__ __forceinline__ uint32_t swz(uint32_t r, uint32_t kc) {
    return r * 128 + ((kc ^ (r & 7)) << 4);
}

// ====== bf16 mma.sync GEMM core (unchanged) ======
template <int NT>
__device__ __forceinline__ void gemm_core(const bf16* __restrict__ A, int lda,
                                          const bf16* __restrict__ B, int ldb,
                                          float (&acc)[4][8][4]) {
    extern __shared__ char sh[];
    const uint32_t sbase = smem_u32(sh);
    const int tid = threadIdx.x, lane = tid & 31, wid = tid >> 5;
    const int wm = wid >> 1, wn = wid & 1;
    const int dl  = (lane & 7) + ((lane >> 3) & 1) * 8;
    const int dkc = lane >> 4;

    auto load_stage = [&](int s, int t) {
        uint32_t ab = sbase + s * STAGE_B;
        uint32_t bb = ab + TILE_B;
        const bf16* ga = A + t * BKC;
        const bf16* gb = B + t * BKC;
        #pragma unroll
        for (int it = 0; it < 8; it++) {
            int c = tid + it * 128;
            int r = c >> 3, kc = c & 7;
            uint32_t o = swz(r, kc);
            cpa16(ab + o, ga + (size_t)r * lda + kc * 8);
            cpa16(bb + o, gb + (size_t)r * ldb + kc * 8);
        }
        asm volatile("cp.async.commit_group;");
    };

    load_stage(0, 0);
    if (NT > 1) load_stage(1, 1);

    #pragma unroll 1
    for (int t = 0; t < NT; t++) {
        if (t + 1 < NT) asm volatile("cp.async.wait_group 1;");
        else            asm volatile("cp.async.wait_group 0;");
        __syncthreads();
        if (t + 2 < NT) load_stage((t + 2) % NSG, t + 2);

        uint32_t ab = sbase + (t % NSG) * STAGE_B;
        uint32_t bb = ab + TILE_B;
        #pragma unroll
        for (int ks = 0; ks < 4; ks++) {
            uint32_t a[4][4], b2[4][4];
            #pragma unroll
            for (int i = 0; i < 4; i++)
                ldmx4(a[i], ab + swz(wm * 64 + i * 16 + dl, ks * 2 + dkc));
            #pragma unroll
            for (int jj = 0; jj < 4; jj++)
                ldmx4(b2[jj], bb + swz(wn * 64 + jj * 16 + dl, ks * 2 + dkc));
            #pragma unroll
            for (int i = 0; i < 4; i++)
                #pragma unroll
                for (int j = 0; j < 8; j++)
                    mma_bf16(acc[i][j], a[i], b2[j >> 1][j & 1], b2[j >> 1][(j & 1) + 2]);
        }
    }
}

// ============ fused GroupNorm stats + normalize + transpose ============
__global__ __launch_bounds__(256) void gnht(const float* __restrict__ x,
                                            const float* __restrict__ nw,
                                            const float* __restrict__ nb) {
    extern __shared__ char shraw[];
    bf16* sb = (bf16*)shraw;
    __shared__ float red_s[8], red_q[8], ssc[CPG], ssh[CPG];
    const int bg = blockIdx.x;
    const int b = bg / GROUPS, g = bg % GROUPS;
    const int tid = threadIdx.x;
    const float4* p4 = (const float4*)(x + ((size_t)b * CH + (size_t)g * CPG) * NPIX);

    float s = 0.f, sq = 0.f;
    #pragma unroll 4
    for (int i = 0; i < 32; i++) {
        int idx = tid + i * 256;
        float4 v = p4[idx];
        s += v.x + v.y + v.z + v.w;
        sq += v.x * v.x + v.y * v.y + v.z * v.z + v.w * v.w;
        int c = idx >> 8, n4 = idx & 255;
        uint32_t base = c * HT_STRIDE + n4 * 4;
        *(uint32_t*)&sb[base]     = pk2(v.x, v.y);
        *(uint32_t*)&sb[base + 2] = pk2(v.z, v.w);
    }
    #pragma unroll
    for (int o = 16; o; o >>= 1) {
        s  += __shfl_xor_sync(~0u, s, o);
        sq += __shfl_xor_sync(~0u, sq, o);
    }
    if ((tid & 31) == 0) { red_s[tid >> 5] = s; red_q[tid >> 5] = sq; }
    __syncthreads();
    if (tid < CPG) {
        float st = 0.f, qt = 0.f;
        #pragma unroll
        for (int i = 0; i < 8; i++) { st += red_s[i]; qt += red_q[i]; }
        const float inv_n = 1.f / (float)(CPG * NPIX);
        float mean = st * inv_n;
        float var  = qt * inv_n - mean * mean;
        float rstd = rsqrtf(var + EPSV);
        int c = g * CPG + tid;
        float sc = rstd * nw[c];
        ssc[tid] = sc;
        ssh[tid] = nb[c] - mean * sc;
    }
    __syncthreads();

    bf16* dst = g_hT + (size_t)b * NPIX * CH + g * CPG;
    const int cq = tid & 7, nb0 = tid >> 3;
    const float sc0 = ssc[cq * 4], sc1 = ssc[cq * 4 + 1], sc2 = ssc[cq * 4 + 2], sc3 = ssc[cq * 4 + 3];
    const float sh0 = ssh[cq * 4], sh1 = ssh[cq * 4 + 1], sh2 = ssh[cq * 4 + 2], sh3 = ssh[cq * 4 + 3];
    #pragma unroll 4
    for (int i = 0; i < 32; i++) {
        int n = nb0 + i * 32;
        float x0 = __bfloat162float(sb[(cq * 4 + 0) * HT_STRIDE + n]);
        float x1 = __bfloat162float(sb[(cq * 4 + 1) * HT_STRIDE + n]);
        float x2 = __bfloat162float(sb[(cq * 4 + 2) * HT_STRIDE + n]);
        float x3 = __bfloat162float(sb[(cq * 4 + 3) * HT_STRIDE + n]);
        uint2 w;
        w.x = pk2(fmaf(x0, sc0, sh0), fmaf(x1, sc1, sh1));
        w.y = pk2(fmaf(x2, sc2, sh2), fmaf(x3, sc3, sh3));
        *(uint2*)&dst[(size_t)n * CH + cq * 4] = w;
    }
}

// ================= weights -> bf16 (q rows pre-scaled log2e/16) =================
__global__ __launch_bounds__(256) void wcvt(const float* __restrict__ qkv_w,
                                            const float* __restrict__ proj_w) {
    int idx = blockIdx.x * 256 + threadIdx.x;
    #pragma unroll
    for (int u = 0; u < 4; u++) {
        int e = idx * 4 + u;
        if (e < 768 * CH) {
            int row = e / CH;
            float v = qkv_w[e];
            if (row < CH) v *= 0.0625f * 1.44269504f;
            if (row < 512) g_wqk[e] = __float2bfloat16(v);
            else           g_wv[e - 512 * CH] = __float2bfloat16(v);
        } else {
            int e2 = e - 768 * CH;
            g_wp[e2] = __float2bfloat16(proj_w[e2]);
        }
    }
}

// ========== merged QKV GEMM ==========
__global__ __launch_bounds__(128, 2) void qkv_gemm() {
    const int b = blockIdx.z;
    const int wid = threadIdx.x >> 5, lane = threadIdx.x & 31, gr = lane >> 2, tg = lane & 3;
    const int wm = wid >> 1, wn = wid & 1;
    float acc[4][8][4] = {};

    if (blockIdx.y < 4) {
        const int m0 = blockIdx.x * 128;
        const int n0 = blockIdx.y * 128;
        gemm_core<CH / BKC>(g_hT + (size_t)b * NPIX * CH + (size_t)m0 * CH, CH,
                            g_wqk + (size_t)n0 * CH, CH, acc);
        bf16* dst = (n0 < 256 ? g_qT : g_kT) + (size_t)b * NPIX * CH;
        const int c0 = n0 & 255;
        #pragma unroll
        for (int i = 0; i < 4; i++) {
            int row = m0 + wm * 64 + i * 16 + gr;
            #pragma unroll
            for (int j = 0; j < 8; j++) {
                int col = c0 + wn * 64 + j * 8 + tg * 2;
                *(uint32_t*)&dst[(size_t)row * CH + col]       = pk2(acc[i][j][0], acc[i][j][1]);
                *(uint32_t*)&dst[(size_t)(row + 8) * CH + col] = pk2(acc[i][j][2], acc[i][j][3]);
            }
        }
    } else {
        const int m0 = (blockIdx.y - 4) * 128;
        const int n0 = blockIdx.x * 128;
        gemm_core<CH / BKC>(g_wv + (size_t)m0 * CH, CH,
                            g_hT + (size_t)b * NPIX * CH + (size_t)n0 * CH, CH, acc);
        bf16* dst = g_v + (size_t)b * CH * NPIX;
        #pragma unroll
        for (int i = 0; i < 4; i++) {
            int row = m0 + wm * 64 + i * 16 + gr;
            #pragma unroll
            for (int j = 0; j < 8; j++) {
                int col = n0 + wn * 64 + j * 8 + tg * 2;
                *(uint32_t*)&dst[(size_t)row * NPIX + col]       = pk2(acc[i][j][0], acc[i][j][1]);
                *(uint32_t*)&dst[(size_t)(row + 8) * NPIX + col] = pk2(acc[i][j][2], acc[i][j][3]);
            }
        }
    }
}

// ========== fused flash attention + proj + bias + residual ==========
// grid (16, BATCH), 128 threads (4 warps x 16 q rows).
// Mainloop SMEM: Q 32K | K 32K | V 32K. Epilogue reuses: out 32K | Wp 32K | Wp 32K.
__global__ __launch_bounds__(128, 2) void flash_attn(const float* __restrict__ x,
                                                     const float* __restrict__ pb,
                                                     float* __restrict__ y) {
    extern __shared__ char sh[];
    __shared__ float pb_s[CH];
    const uint32_t sq = smem_u32(sh);
    const uint32_t sk = sq + 32768;
    const uint32_t sv = sq + 65536;
    const int b = blockIdx.y, nblk = blockIdx.x * 64;
    const int tid = threadIdx.x, lane = tid & 31, wid = tid >> 5;
    const int q0 = wid * 16;
    const int gr = lane >> 2, tg = lane & 3;
    const int dl = lane & 15, dkc = lane >> 4;

    pb_s[tid] = pb[tid];
    pb_s[tid + 128] = pb[tid + 128];

    const bf16* Qg = g_qT + (size_t)b * NPIX * CH + (size_t)nblk * CH;
    const bf16* Kg = g_kT + (size_t)b * NPIX * CH;
    const bf16* Vg = g_v  + (size_t)b * CH * NPIX;

    auto load_k = [&](int j) {
        #pragma unroll
        for (int it = 0; it < 16; it++) {
            int c = tid + it * 128;
            int p = c >> 9, rr = (c >> 3) & 63, kc = c & 7;
            cpa16(sk + p * 8192 + swz(rr, kc),
                  Kg + (size_t)(j * 64 + rr) * CH + p * 64 + kc * 8);
        }
        asm volatile("cp.async.commit_group;");
    };
    auto load_v = [&](int j) {
        #pragma unroll
        for (int it = 0; it < 16; it++) {
            int c = tid + it * 128;
            int rr = c >> 3, kc = c & 7;
            cpa16(sv + swz(rr, kc),
                  Vg + (size_t)rr * NPIX + j * 64 + kc * 8);
        }
        asm volatile("cp.async.commit_group;");
    };

    {
        #pragma unroll
        for (int it = 0; it < 16; it++) {
            int c = tid + it * 128;
            int p = c >> 9, rr = (c >> 3) & 63, kc = c & 7;
            cpa16(sq + p * 8192 + swz(rr, kc), Qg + (size_t)rr * CH + p * 64 + kc * 8);
            cpa16(sk + p * 8192 + swz(rr, kc), Kg + (size_t)rr * CH + p * 64 + kc * 8);
        }
        asm volatile("cp.async.commit_group;");
    }
    load_v(0);
    asm volatile("cp.async.wait_group 1;");
    __syncthreads();

    float oacc[32][4] = {};
    float m0 = -1e30f, m1 = -1e30f, l0 = 0.f, l1 = 0.f;

    #pragma unroll 1
    for (int j = 0; j < 16; j++) {
        float sacc[8][4];
        #pragma unroll
        for (int t = 0; t < 8; t++)
            sacc[t][0] = sacc[t][1] = sacc[t][2] = sacc[t][3] = 0.f;
        #pragma unroll
        for (int ks = 0; ks < 16; ks++) {
            uint32_t a[4];
            ldmx4(a, sq + (ks >> 2) * 8192 + swz(q0 + dl, ((ks & 3) << 1) + dkc));
            #pragma unroll
            for (int jj = 0; jj < 4; jj++) {
                uint32_t bb[4];
                ldmx4(bb, sk + (ks >> 2) * 8192 + swz(jj * 16 + dl, ((ks & 3) << 1) + dkc));
                mma_bf16(sacc[2 * jj],     a, bb[0], bb[2]);
                mma_bf16(sacc[2 * jj + 1], a, bb[1], bb[3]);
            }
        }
        // online softmax (exp2 domain)
        float rx0 = -1e30f, rx1 = -1e30f;
        #pragma unroll
        for (int t = 0; t < 8; t++) {
            rx0 = fmaxf(rx0, fmaxf(sacc[t][0], sacc[t][1]));
            rx1 = fmaxf(rx1, fmaxf(sacc[t][2], sacc[t][3]));
        }
        rx0 = fmaxf(rx0, __shfl_xor_sync(~0u, rx0, 1)); rx0 = fmaxf(rx0, __shfl_xor_sync(~0u, rx0, 2));
        rx1 = fmaxf(rx1, __shfl_xor_sync(~0u, rx1, 1)); rx1 = fmaxf(rx1, __shfl_xor_sync(~0u, rx1, 2));
        float mn0 = fmaxf(m0, rx0), mn1 = fmaxf(m1, rx1);
        float al0 = exp2f(m0 - mn0), al1 = exp2f(m1 - mn1);
        m0 = mn0; m1 = mn1;
        float rs0 = 0.f, rs1 = 0.f;
        #pragma unroll
        for (int t = 0; t < 8; t++) {
            sacc[t][0] = exp2f(sacc[t][0] - mn0); rs0 += sacc[t][0];
            sacc[t][1] = exp2f(sacc[t][1] - mn0); rs0 += sacc[t][1];
            sacc[t][2] = exp2f(sacc[t][2] - mn1); rs1 += sacc[t][2];
            sacc[t][3] = exp2f(sacc[t][3] - mn1); rs1 += sacc[t][3];
        }
        l0 = l0 * al0 + rs0;
        l1 = l1 * al1 + rs1;
        if (al0 != 1.0f || al1 != 1.0f) {       // skip rescale when max unchanged
            #pragma unroll
            for (int t = 0; t < 32; t++) {
                oacc[t][0] *= al0; oacc[t][1] *= al0;
                oacc[t][2] *= al1; oacc[t][3] *= al1;
            }
        }

        __syncthreads();
        if (j < 15) load_k(j + 1);
        if (j < 15) asm volatile("cp.async.wait_group 1;");
        else        asm volatile("cp.async.wait_group 0;");
        __syncthreads();

        #pragma unroll
        for (int kp = 0; kp < 4; kp++) {
            uint32_t a[4];
            a[0] = pk2(sacc[2 * kp][0],     sacc[2 * kp][1]);
            a[1] = pk2(sacc[2 * kp][2],     sacc[2 * kp][3]);
            a[2] = pk2(sacc[2 * kp + 1][0], sacc[2 * kp + 1][1]);
            a[3] = pk2(sacc[2 * kp + 1][2], sacc[2 * kp + 1][3]);
            #pragma unroll
            for (int cc = 0; cc < 16; cc++) {
                uint32_t bb[4];
                ldmx4(bb, sv + swz(cc * 16 + dl, kp * 2 + dkc));
                mma_bf16(oacc[2 * cc],     a, bb[0], bb[2]);
                mma_bf16(oacc[2 * cc + 1], a, bb[1], bb[3]);
            }
        }
        __syncthreads();
        if (j < 15) {
            load_v(j + 1);
            asm volatile("cp.async.wait_group 1;");
            __syncthreads();
        }
    }

    // ===== epilogue 1: normalize, store out tile to sq region (bf16, A layout) =====
    l0 += __shfl_xor_sync(~0u, l0, 1); l0 += __shfl_xor_sync(~0u, l0, 2);
    l1 += __shfl_xor_sync(~0u, l1, 1); l1 += __shfl_xor_sync(~0u, l1, 2);
    float inv0 = 1.f / l0, inv1 = 1.f / l1;
    const int row0l = q0 + gr, row1l = row0l + 8;
    #pragma unroll
    for (int t = 0; t < 32; t++) {
        int col = t * 8 + tg * 2;
        int panel = col >> 6;
        uint32_t kc = (uint32_t)(col & 63) >> 3;        // 16B chunk
        uint32_t wb = ((uint32_t)col & 7) * 2;          // byte within chunk
        sts32(sq + panel * 8192 + (uint32_t)row0l * 128 + ((kc ^ (row0l & 7)) << 4) + wb,
              pk2(oacc[t][0] * inv0, oacc[t][1] * inv0));
        sts32(sq + panel * 8192 + (uint32_t)row1l * 128 + ((kc ^ (row1l & 7)) << 4) + wb,
              pk2(oacc[t][2] * inv1, oacc[t][3] * inv1));
    }

    // ===== epilogue 2: proj GEMM  D[64n x 256o] = out[64n x 256k] · Wp[o,k] =====
    auto load_wp = [&](uint32_t dstbase, int ch) {
        const bf16* W = g_wp + (size_t)ch * 64 * CH;
        #pragma unroll
        for (int it = 0; it < 16; it++) {
            int c = tid + it * 128;
            int p = c >> 9, rr = (c >> 3) & 63, kc = c & 7;
            cpa16(dstbase + p * 8192 + swz(rr, kc), W + (size_t)rr * CH + p * 64 + kc * 8);
        }
        asm volatile("cp.async.commit_group;");
    };
    load_wp(sk, 0);
    load_wp(sv, 1);

    float acc2[32][4] = {};
    #pragma unroll 1
    for (int ch = 0; ch < 4; ch++) {
        if (ch < 3) asm volatile("cp.async.wait_group 1;");
        else        asm volatile("cp.async.wait_group 0;");
        __syncthreads();   // Wp chunk + (first iter) out tile visible
        uint32_t buf = (ch & 1) ? sv : sk;
        #pragma unroll
        for (int ks = 0; ks < 16; ks++) {
            uint32_t a[4];
            ldmx4(a, sq + (ks >> 2) * 8192 + swz(q0 + dl, ((ks & 3) << 1) + dkc));
            #pragma unroll
            for (int g = 0; g < 4; g++) {
                uint32_t bb[4];
                ldmx4(bb, buf + (ks >> 2) * 8192 + swz(g * 16 + dl, ((ks & 3) << 1) + dkc));
                mma_bf16(acc2[ch * 8 + g * 2],     a, bb[0], bb[2]);
                mma_bf16(acc2[ch * 8 + g * 2 + 1], a, bb[1], bb[3]);
            }
        }
        if (ch < 2) {
            __syncthreads();           // all warps done reading buf
            load_wp(buf, ch + 2);
        }
    }

    // ===== epilogue 3: y[o][n] = x[o][n] + pb[o] + acc2 =====
    const float* xb = x + (size_t)b * CH * NPIX;
    float* yb = y + (size_t)b * CH * NPIX;
    const int n0g = nblk + q0 + gr, n1g = n0g + 8;
    #pragma unroll
    for (int jt = 0; jt < 32; jt++) {
        int o = (jt >> 3) * 64 + (jt & 7) * 8 + tg * 2;
        float p0 = pb_s[o], p1 = pb_s[o + 1];
        size_t i00 = (size_t)o * NPIX + n0g;
        size_t i01 = (size_t)(o + 1) * NPIX + n0g;
        size_t i10 = (size_t)o * NPIX + n1g;
        size_t i11 = (size_t)(o + 1) * NPIX + n1g;
        yb[i00] = xb[i00] + p0 + acc2[jt][0];
        yb[i01] = xb[i01] + p1 + acc2[jt][1];
        yb[i10] = xb[i10] + p0 + acc2[jt][2];
        yb[i11] = xb[i11] + p1 + acc2[jt][3];
    }
}

extern "C" void kernel_launch(void* const* d_in, const int* in_sizes, int n_in,
                              void* d_out, int out_size) {
    const float* x      = (const float*)d_in[0];
    const float* norm_w = (const float*)d_in[1];
    const float* norm_b = (const float*)d_in[2];
    const float* qkv_w  = (const float*)d_in[3];
    const float* proj_w = (const float*)d_in[4];
    const float* proj_b = (const float*)d_in[5];
    float* y = (float*)d_out;

    cudaFuncSetAttribute(gnht,       cudaFuncAttributeMaxDynamicSharedMemorySize, GNHT_SMEM);
    cudaFuncSetAttribute(qkv_gemm,   cudaFuncAttributeMaxDynamicSharedMemorySize, SMEM_REQ);
    cudaFuncSetAttribute(flash_attn, cudaFuncAttributeMaxDynamicSharedMemorySize, FA_SMEM);

    wcvt<<<(1024 * CH) / (256 * 4), 256>>>(qkv_w, proj_w);
    gnht<<<BATCH * GROUPS, 256, GNHT_SMEM>>>(x, norm_w, norm_b);
    qkv_gemm<<<dim3(NPIX / 128, 6, BATCH), 128, SMEM_REQ>>>();
    flash_attn<<<dim3(NPIX / 64, BATCH), 128, FA_SMEM>>>(x, proj_b, y);
}

// round 12
// speedup vs baseline: 1.0288x; 1.0288x over previous
#include <cuda_runtime.h>
#include <cuda_bf16.h>
#include <stdint.h>

#define BATCH 32
#define CH    256
#define NPIX  1024
#define GROUPS 8
#define CPG   32
#define EPSV  1e-5f

#define BKC 64
#define TILE_B  16384
#define STAGE_B (2 * TILE_B)
#define NSG 3
#define SMEM_REQ (NSG * STAGE_B)     // 98304 for gemm kernels
#define FA_SMEM 98304                // 96KB: Q 32K + K 32K + V 32K -> 2 CTAs/SM
#define HT_STRIDE 1042               // bf16 per smem row (coprime banks)
#define GNHT_SMEM (CPG * HT_STRIDE * 2)   // 66688 B

typedef __nv_bfloat16 bf16;

// ---- scratch ----
__device__ bf16 g_hT [(size_t)BATCH * NPIX * CH];
__device__ bf16 g_qT [(size_t)BATCH * NPIX * CH];    // [b][n][c] (W_q pre-scaled log2e/16)
__device__ bf16 g_kT [(size_t)BATCH * NPIX * CH];    // [b][m][c]
__device__ bf16 g_v  [(size_t)BATCH * CH * NPIX];    // [b][c][m]
__device__ bf16 g_out[(size_t)BATCH * NPIX * CH];    // [b][n][c]
__device__ bf16 g_wqk[(size_t)512 * CH];
__device__ bf16 g_wv [(size_t)CH * CH];
__device__ bf16 g_wp [(size_t)CH * CH];

// ================= helpers =================
__device__ __forceinline__ uint32_t smem_u32(const void* p) {
    uint32_t a;
    asm("{ .reg .u64 t; cvta.to.shared.u64 t, %1; cvt.u32.u64 %0, t; }" : "=r"(a) : "l"(p));
    return a;
}
__device__ __forceinline__ void cpa16(uint32_t d, const void* s) {
    asm volatile("cp.async.cg.shared.global [%0], [%1], 16;" :: "r"(d), "l"(s));
}
__device__ __forceinline__ uint32_t pk2(float lo, float hi) {
    uint32_t r;
    asm("cvt.rn.bf16x2.f32 %0, %1, %2;" : "=r"(r) : "f"(hi), "f"(lo));
    return r;
}
__device__ __forceinline__ void mma_bf16(float c[4], const uint32_t a[4], uint32_t b0, uint32_t b1) {
    asm volatile("mma.sync.aligned.m16n8k16.row.col.f32.bf16.bf16.f32 "
                 "{%0,%1,%2,%3}, {%4,%5,%6,%7}, {%8,%9}, {%0,%1,%2,%3};\n"
                 : "+f"(c[0]), "+f"(c[1]), "+f"(c[2]), "+f"(c[3])
                 : "r"(a[0]), "r"(a[1]), "r"(a[2]), "r"(a[3]), "r"(b0), "r"(b1));
}
__device__ __forceinline__ void ldmx4(uint32_t r[4], uint32_t addr) {
    asm volatile("ldmatrix.sync.aligned.m8n8.x4.shared.b16 {%0,%1,%2,%3}, [%4];"
                 : "=r"(r[0]), "=r"(r[1]), "=r"(r[2]), "=r"(r[3]) : "r"(addr));
}
// 128B-row swizzle: row r, 16B chunk kc in [0,8)
__device__ __forceinline__ uint32_t swz(uint32_t r, uint32_t kc) {
    return r * 128 + ((kc ^ (r & 7)) << 4);
}

// ====== bf16 mma.sync GEMM core ======
template <int NT>
__device__ __forceinline__ void gemm_core(const bf16* __restrict__ A, int lda,
                                          const bf16* __restrict__ B, int ldb,
                                          float (&acc)[4][8][4]) {
    extern __shared__ char sh[];
    const uint32_t sbase = smem_u32(sh);
    const int tid = threadIdx.x, lane = tid & 31, wid = tid >> 5;
    const int wm = wid >> 1, wn = wid & 1;
    const int dl  = (lane & 7) + ((lane >> 3) & 1) * 8;
    const int dkc = lane >> 4;

    auto load_stage = [&](int s, int t) {
        uint32_t ab = sbase + s * STAGE_B;
        uint32_t bb = ab + TILE_B;
        const bf16* ga = A + t * BKC;
        const bf16* gb = B + t * BKC;
        #pragma unroll
        for (int it = 0; it < 8; it++) {
            int c = tid + it * 128;
            int r = c >> 3, kc = c & 7;
            uint32_t o = swz(r, kc);
            cpa16(ab + o, ga + (size_t)r * lda + kc * 8);
            cpa16(bb + o, gb + (size_t)r * ldb + kc * 8);
        }
        asm volatile("cp.async.commit_group;");
    };

    load_stage(0, 0);
    if (NT > 1) load_stage(1, 1);

    #pragma unroll 1
    for (int t = 0; t < NT; t++) {
        if (t + 1 < NT) asm volatile("cp.async.wait_group 1;");
        else            asm volatile("cp.async.wait_group 0;");
        __syncthreads();
        if (t + 2 < NT) load_stage((t + 2) % NSG, t + 2);

        uint32_t ab = sbase + (t % NSG) * STAGE_B;
        uint32_t bb = ab + TILE_B;
        #pragma unroll
        for (int ks = 0; ks < 4; ks++) {
            uint32_t a[4][4], b2[4][4];
            #pragma unroll
            for (int i = 0; i < 4; i++)
                ldmx4(a[i], ab + swz(wm * 64 + i * 16 + dl, ks * 2 + dkc));
            #pragma unroll
            for (int jj = 0; jj < 4; jj++)
                ldmx4(b2[jj], bb + swz(wn * 64 + jj * 16 + dl, ks * 2 + dkc));
            #pragma unroll
            for (int i = 0; i < 4; i++)
                #pragma unroll
                for (int j = 0; j < 8; j++)
                    mma_bf16(acc[i][j], a[i], b2[j >> 1][j & 1], b2[j >> 1][(j & 1) + 2]);
        }
    }
}

// ============ fused GroupNorm stats + normalize + transpose ============
__global__ __launch_bounds__(256) void gnht(const float* __restrict__ x,
                                            const float* __restrict__ nw,
                                            const float* __restrict__ nb) {
    extern __shared__ char shraw[];
    bf16* sb = (bf16*)shraw;
    __shared__ float red_s[8], red_q[8], ssc[CPG], ssh[CPG];
    const int bg = blockIdx.x;
    const int b = bg / GROUPS, g = bg % GROUPS;
    const int tid = threadIdx.x;
    const float4* p4 = (const float4*)(x + ((size_t)b * CH + (size_t)g * CPG) * NPIX);

    float s = 0.f, sq = 0.f;
    #pragma unroll 4
    for (int i = 0; i < 32; i++) {
        int idx = tid + i * 256;
        float4 v = p4[idx];
        s += v.x + v.y + v.z + v.w;
        sq += v.x * v.x + v.y * v.y + v.z * v.z + v.w * v.w;
        int c = idx >> 8, n4 = idx & 255;
        uint32_t base = c * HT_STRIDE + n4 * 4;
        *(uint32_t*)&sb[base]     = pk2(v.x, v.y);
        *(uint32_t*)&sb[base + 2] = pk2(v.z, v.w);
    }
    #pragma unroll
    for (int o = 16; o; o >>= 1) {
        s  += __shfl_xor_sync(~0u, s, o);
        sq += __shfl_xor_sync(~0u, sq, o);
    }
    if ((tid & 31) == 0) { red_s[tid >> 5] = s; red_q[tid >> 5] = sq; }
    __syncthreads();
    if (tid < CPG) {
        float st = 0.f, qt = 0.f;
        #pragma unroll
        for (int i = 0; i < 8; i++) { st += red_s[i]; qt += red_q[i]; }
        const float inv_n = 1.f / (float)(CPG * NPIX);
        float mean = st * inv_n;
        float var  = qt * inv_n - mean * mean;
        float rstd = rsqrtf(var + EPSV);
        int c = g * CPG + tid;
        float sc = rstd * nw[c];
        ssc[tid] = sc;
        ssh[tid] = nb[c] - mean * sc;
    }
    __syncthreads();

    bf16* dst = g_hT + (size_t)b * NPIX * CH + g * CPG;
    const int cq = tid & 7, nb0 = tid >> 3;
    const float sc0 = ssc[cq * 4], sc1 = ssc[cq * 4 + 1], sc2 = ssc[cq * 4 + 2], sc3 = ssc[cq * 4 + 3];
    const float sh0 = ssh[cq * 4], sh1 = ssh[cq * 4 + 1], sh2 = ssh[cq * 4 + 2], sh3 = ssh[cq * 4 + 3];
    #pragma unroll 4
    for (int i = 0; i < 32; i++) {
        int n = nb0 + i * 32;
        float x0 = __bfloat162float(sb[(cq * 4 + 0) * HT_STRIDE + n]);
        float x1 = __bfloat162float(sb[(cq * 4 + 1) * HT_STRIDE + n]);
        float x2 = __bfloat162float(sb[(cq * 4 + 2) * HT_STRIDE + n]);
        float x3 = __bfloat162float(sb[(cq * 4 + 3) * HT_STRIDE + n]);
        uint2 w;
        w.x = pk2(fmaf(x0, sc0, sh0), fmaf(x1, sc1, sh1));
        w.y = pk2(fmaf(x2, sc2, sh2), fmaf(x3, sc3, sh3));
        *(uint2*)&dst[(size_t)n * CH + cq * 4] = w;
    }
}

// ================= weights -> bf16 (q rows pre-scaled log2e/16) =================
__global__ __launch_bounds__(256) void wcvt(const float* __restrict__ qkv_w,
                                            const float* __restrict__ proj_w) {
    int idx = blockIdx.x * 256 + threadIdx.x;
    #pragma unroll
    for (int u = 0; u < 4; u++) {
        int e = idx * 4 + u;
        if (e < 768 * CH) {
            int row = e / CH;
            float v = qkv_w[e];
            if (row < CH) v *= 0.0625f * 1.44269504f;   // 1/16 * log2(e)
            if (row < 512) g_wqk[e] = __float2bfloat16(v);
            else           g_wv[e - 512 * CH] = __float2bfloat16(v);
        } else {
            int e2 = e - 768 * CH;
            g_wp[e2] = __float2bfloat16(proj_w[e2]);
        }
    }
}

// ========== merged QKV GEMM: y<4 -> q/k path, y>=4 -> v path ==========
__global__ __launch_bounds__(128, 2) void qkv_gemm() {
    const int b = blockIdx.z;
    const int wid = threadIdx.x >> 5, lane = threadIdx.x & 31, gr = lane >> 2, tg = lane & 3;
    const int wm = wid >> 1, wn = wid & 1;
    float acc[4][8][4] = {};

    if (blockIdx.y < 4) {
        const int m0 = blockIdx.x * 128;
        const int n0 = blockIdx.y * 128;
        gemm_core<CH / BKC>(g_hT + (size_t)b * NPIX * CH + (size_t)m0 * CH, CH,
                            g_wqk + (size_t)n0 * CH, CH, acc);
        bf16* dst = (n0 < 256 ? g_qT : g_kT) + (size_t)b * NPIX * CH;
        const int c0 = n0 & 255;
        #pragma unroll
        for (int i = 0; i < 4; i++) {
            int row = m0 + wm * 64 + i * 16 + gr;
            #pragma unroll
            for (int j = 0; j < 8; j++) {
                int col = c0 + wn * 64 + j * 8 + tg * 2;
                *(uint32_t*)&dst[(size_t)row * CH + col]       = pk2(acc[i][j][0], acc[i][j][1]);
                *(uint32_t*)&dst[(size_t)(row + 8) * CH + col] = pk2(acc[i][j][2], acc[i][j][3]);
            }
        }
    } else {
        const int m0 = (blockIdx.y - 4) * 128;
        const int n0 = blockIdx.x * 128;
        gemm_core<CH / BKC>(g_wv + (size_t)m0 * CH, CH,
                            g_hT + (size_t)b * NPIX * CH + (size_t)n0 * CH, CH, acc);
        bf16* dst = g_v + (size_t)b * CH * NPIX;
        #pragma unroll
        for (int i = 0; i < 4; i++) {
            int row = m0 + wm * 64 + i * 16 + gr;
            #pragma unroll
            for (int j = 0; j < 8; j++) {
                int col = n0 + wn * 64 + j * 8 + tg * 2;
                *(uint32_t*)&dst[(size_t)row * NPIX + col]       = pk2(acc[i][j][0], acc[i][j][1]);
                *(uint32_t*)&dst[(size_t)(row + 8) * NPIX + col] = pk2(acc[i][j][2], acc[i][j][3]);
            }
        }
    }
}

// ========== fused flash attention: 64-row Q blocks, 64-wide K/V blocks ==========
__global__ __launch_bounds__(128, 2) void flash_attn() {
    extern __shared__ char sh[];
    const uint32_t sq = smem_u32(sh);
    const uint32_t sk = sq + 32768;
    const uint32_t sv = sq + 65536;
    const int b = blockIdx.y, nblk = blockIdx.x * 64;
    const int tid = threadIdx.x, lane = tid & 31, wid = tid >> 5;
    const int q0 = wid * 16;
    const int gr = lane >> 2, tg = lane & 3;
    const int dl = lane & 15, dkc = lane >> 4;

    const bf16* Qg = g_qT + (size_t)b * NPIX * CH + (size_t)nblk * CH;
    const bf16* Kg = g_kT + (size_t)b * NPIX * CH;
    const bf16* Vg = g_v  + (size_t)b * CH * NPIX;

    auto load_k = [&](int j) {
        #pragma unroll
        for (int it = 0; it < 16; it++) {
            int c = tid + it * 128;
            int p = c >> 9, rr = (c >> 3) & 63, kc = c & 7;
            cpa16(sk + p * 8192 + swz(rr, kc),
                  Kg + (size_t)(j * 64 + rr) * CH + p * 64 + kc * 8);
        }
        asm volatile("cp.async.commit_group;");
    };
    auto load_v = [&](int j) {
        #pragma unroll
        for (int it = 0; it < 16; it++) {
            int c = tid + it * 128;
            int rr = c >> 3, kc = c & 7;
            cpa16(sv + swz(rr, kc),
                  Vg + (size_t)rr * NPIX + j * 64 + kc * 8);
        }
        asm volatile("cp.async.commit_group;");
    };

    {
        #pragma unroll
        for (int it = 0; it < 16; it++) {
            int c = tid + it * 128;
            int p = c >> 9, rr = (c >> 3) & 63, kc = c & 7;
            cpa16(sq + p * 8192 + swz(rr, kc), Qg + (size_t)rr * CH + p * 64 + kc * 8);
            cpa16(sk + p * 8192 + swz(rr, kc), Kg + (size_t)rr * CH + p * 64 + kc * 8);
        }
        asm volatile("cp.async.commit_group;");
    }
    load_v(0);
    asm volatile("cp.async.wait_group 1;");
    __syncthreads();

    float oacc[32][4] = {};
    float m0 = -1e30f, m1 = -1e30f, l0 = 0.f, l1 = 0.f;

    #pragma unroll 1
    for (int j = 0; j < 16; j++) {
        float sacc[8][4];
        #pragma unroll
        for (int t = 0; t < 8; t++)
            sacc[t][0] = sacc[t][1] = sacc[t][2] = sacc[t][3] = 0.f;
        #pragma unroll
        for (int ks = 0; ks < 16; ks++) {
            uint32_t a[4];
            ldmx4(a, sq + (ks >> 2) * 8192 + swz(q0 + dl, ((ks & 3) << 1) + dkc));
            #pragma unroll
            for (int jj = 0; jj < 4; jj++) {
                uint32_t bb[4];
                ldmx4(bb, sk + (ks >> 2) * 8192 + swz(jj * 16 + dl, ((ks & 3) << 1) + dkc));
                mma_bf16(sacc[2 * jj],     a, bb[0], bb[2]);
                mma_bf16(sacc[2 * jj + 1], a, bb[1], bb[3]);
            }
        }
        // online softmax (exp2 domain — log2e folded into q)
        float rx0 = -1e30f, rx1 = -1e30f;
        #pragma unroll
        for (int t = 0; t < 8; t++) {
            rx0 = fmaxf(rx0, fmaxf(sacc[t][0], sacc[t][1]));
            rx1 = fmaxf(rx1, fmaxf(sacc[t][2], sacc[t][3]));
        }
        rx0 = fmaxf(rx0, __shfl_xor_sync(~0u, rx0, 1)); rx0 = fmaxf(rx0, __shfl_xor_sync(~0u, rx0, 2));
        rx1 = fmaxf(rx1, __shfl_xor_sync(~0u, rx1, 1)); rx1 = fmaxf(rx1, __shfl_xor_sync(~0u, rx1, 2));
        float mn0 = fmaxf(m0, rx0), mn1 = fmaxf(m1, rx1);
        float al0 = exp2f(m0 - mn0), al1 = exp2f(m1 - mn1);
        m0 = mn0; m1 = mn1;
        float rs0 = 0.f, rs1 = 0.f;
        #pragma unroll
        for (int t = 0; t < 8; t++) {
            sacc[t][0] = exp2f(sacc[t][0] - mn0); rs0 += sacc[t][0];
            sacc[t][1] = exp2f(sacc[t][1] - mn0); rs0 += sacc[t][1];
            sacc[t][2] = exp2f(sacc[t][2] - mn1); rs1 += sacc[t][2];
            sacc[t][3] = exp2f(sacc[t][3] - mn1); rs1 += sacc[t][3];
        }
        l0 = l0 * al0 + rs0;
        l1 = l1 * al1 + rs1;
        if (al0 != 1.0f || al1 != 1.0f) {     // skip rescale when max unchanged
            #pragma unroll
            for (int t = 0; t < 32; t++) {
                oacc[t][0] *= al0; oacc[t][1] *= al0;
                oacc[t][2] *= al1; oacc[t][3] *= al1;
            }
        }

        __syncthreads();
        if (j < 15) load_k(j + 1);
        if (j < 15) asm volatile("cp.async.wait_group 1;");
        else        asm volatile("cp.async.wait_group 0;");
        __syncthreads();

        #pragma unroll
        for (int kp = 0; kp < 4; kp++) {
            uint32_t a[4];
            a[0] = pk2(sacc[2 * kp][0],     sacc[2 * kp][1]);
            a[1] = pk2(sacc[2 * kp][2],     sacc[2 * kp][3]);
            a[2] = pk2(sacc[2 * kp + 1][0], sacc[2 * kp + 1][1]);
            a[3] = pk2(sacc[2 * kp + 1][2], sacc[2 * kp + 1][3]);
            #pragma unroll
            for (int cc = 0; cc < 16; cc++) {
                uint32_t bb[4];
                ldmx4(bb, sv + swz(cc * 16 + dl, kp * 2 + dkc));
                mma_bf16(oacc[2 * cc],     a, bb[0], bb[2]);
                mma_bf16(oacc[2 * cc + 1], a, bb[1], bb[3]);
            }
        }
        __syncthreads();
        if (j < 15) {
            load_v(j + 1);
            asm volatile("cp.async.wait_group 1;");
            __syncthreads();
        }
    }

    l0 += __shfl_xor_sync(~0u, l0, 1); l0 += __shfl_xor_sync(~0u, l0, 2);
    l1 += __shfl_xor_sync(~0u, l1, 1); l1 += __shfl_xor_sync(~0u, l1, 2);
    float inv0 = 1.f / l0, inv1 = 1.f / l1;
    bf16* dst = g_out + (size_t)b * NPIX * CH;
    int row0 = nblk + q0 + gr, row1 = row0 + 8;
    #pragma unroll
    for (int t = 0; t < 32; t++) {
        int col = t * 8 + tg * 2;
        *(uint32_t*)&dst[(size_t)row0 * CH + col] = pk2(oacc[t][0] * inv0, oacc[t][1] * inv0);
        *(uint32_t*)&dst[(size_t)row1 * CH + col] = pk2(oacc[t][2] * inv1, oacc[t][3] * inv1);
    }
}

// ========== proj: y[o][n] = x + pb[o] + Wp[o,:]·out[n,:] ==========
__global__ __launch_bounds__(128, 2) void proj_gemm(const float* __restrict__ x,
                                                    const float* __restrict__ pb,
                                                    float* __restrict__ y) {
    const int b = blockIdx.z, m0 = blockIdx.y * 128, n0 = blockIdx.x * 128;
    float acc[4][8][4] = {};
    gemm_core<CH / BKC>(g_wp + (size_t)m0 * CH, CH,
                        g_out + (size_t)b * NPIX * CH + (size_t)n0 * CH, CH, acc);
    const int wid = threadIdx.x >> 5, lane = threadIdx.x & 31, gr = lane >> 2, tg = lane & 3;
    const int wm = wid >> 1, wn = wid & 1;
    const float* xb = x + (size_t)b * CH * NPIX;
    float* yb = y + (size_t)b * CH * NPIX;
    #pragma unroll
    for (int i = 0; i < 4; i++) {
        int row = m0 + wm * 64 + i * 16 + gr;
        float b0 = pb[row], b1 = pb[row + 8];
        #pragma unroll
        for (int j = 0; j < 8; j++) {
            int col = n0 + wn * 64 + j * 8 + tg * 2;
            size_t i0 = (size_t)row * NPIX + col;
            size_t i1 = (size_t)(row + 8) * NPIX + col;
            float2 x0 = *(const float2*)&xb[i0];
            float2 x1 = *(const float2*)&xb[i1];
            *(float2*)&yb[i0] = make_float2(x0.x + b0 + acc[i][j][0], x0.y + b0 + acc[i][j][1]);
            *(float2*)&yb[i1] = make_float2(x1.x + b1 + acc[i][j][2], x1.y + b1 + acc[i][j][3]);
        }
    }
}

extern "C" void kernel_launch(void* const* d_in, const int* in_sizes, int n_in,
                              void* d_out, int out_size) {
    const float* x      = (const float*)d_in[0];
    const float* norm_w = (const float*)d_in[1];
    const float* norm_b = (const float*)d_in[2];
    const float* qkv_w  = (const float*)d_in[3];
    const float* proj_w = (const float*)d_in[4];
    const float* proj_b = (const float*)d_in[5];
    float* y = (float*)d_out;

    cudaFuncSetAttribute(gnht,       cudaFuncAttributeMaxDynamicSharedMemorySize, GNHT_SMEM);
    cudaFuncSetAttribute(qkv_gemm,   cudaFuncAttributeMaxDynamicSharedMemorySize, SMEM_REQ);
    cudaFuncSetAttribute(proj_gemm,  cudaFuncAttributeMaxDynamicSharedMemorySize, SMEM_REQ);
    cudaFuncSetAttribute(flash_attn, cudaFuncAttributeMaxDynamicSharedMemorySize, FA_SMEM);

    wcvt<<<(1024 * CH) / (256 * 4), 256>>>(qkv_w, proj_w);
    gnht<<<BATCH * GROUPS, 256, GNHT_SMEM>>>(x, norm_w, norm_b);
    qkv_gemm<<<dim3(NPIX / 128, 6, BATCH), 128, SMEM_REQ>>>();
    flash_attn<<<dim3(NPIX / 64, BATCH), 128, FA_SMEM>>>();
    proj_gemm<<<dim3(NPIX / 128, 2, BATCH), 128, SMEM_REQ>>>(x, proj_b, y);
}

// round 13
// speedup vs baseline: 1.1107x; 1.0796x over previous
#include <cuda_runtime.h>
#include <cuda_bf16.h>
#include <stdint.h>

#define BATCH 32
#define HBATCH 16
#define CH    256
#define NPIX  1024
#define GROUPS 8
#define CPG   32
#define EPSV  1e-5f

#define BKC 64
#define TILE_B  16384
#define STAGE_B (2 * TILE_B)
#define NSG 3
#define SMEM_REQ (NSG * STAGE_B)     // 98304 for gemm kernels
#define FA_SMEM 98304                // 96KB: Q 32K + K 32K + V 32K -> 2 CTAs/SM
#define HT_STRIDE 1042
#define GNHT_SMEM (CPG * HT_STRIDE * 2)

typedef __nv_bfloat16 bf16;

// ---- scratch ----
__device__ bf16 g_hT [(size_t)BATCH * NPIX * CH];
__device__ bf16 g_qT [(size_t)BATCH * NPIX * CH];    // [b][n][c] (W_q pre-scaled log2e/16)
__device__ bf16 g_kT [(size_t)BATCH * NPIX * CH];    // [b][m][c]
__device__ bf16 g_v  [(size_t)BATCH * CH * NPIX];    // [b][c][m]
__device__ bf16 g_out[(size_t)BATCH * NPIX * CH];    // [b][n][c]
__device__ bf16 g_wqk[(size_t)512 * CH];
__device__ bf16 g_wv [(size_t)CH * CH];
__device__ bf16 g_wp [(size_t)CH * CH];

// ================= helpers =================
__device__ __forceinline__ uint32_t smem_u32(const void* p) {
    uint32_t a;
    asm("{ .reg .u64 t; cvta.to.shared.u64 t, %1; cvt.u32.u64 %0, t; }" : "=r"(a) : "l"(p));
    return a;
}
__device__ __forceinline__ void cpa16(uint32_t d, const void* s) {
    asm volatile("cp.async.cg.shared.global [%0], [%1], 16;" :: "r"(d), "l"(s));
}
__device__ __forceinline__ uint32_t pk2(float lo, float hi) {
    uint32_t r;
    asm("cvt.rn.bf16x2.f32 %0, %1, %2;" : "=r"(r) : "f"(hi), "f"(lo));
    return r;
}
__device__ __forceinline__ void mma_bf16(float c[4], const uint32_t a[4], uint32_t b0, uint32_t b1) {
    asm volatile("mma.sync.aligned.m16n8k16.row.col.f32.bf16.bf16.f32 "
                 "{%0,%1,%2,%3}, {%4,%5,%6,%7}, {%8,%9}, {%0,%1,%2,%3};\n"
                 : "+f"(c[0]), "+f"(c[1]), "+f"(c[2]), "+f"(c[3])
                 : "r"(a[0]), "r"(a[1]), "r"(a[2]), "r"(a[3]), "r"(b0), "r"(b1));
}
__device__ __forceinline__ void ldmx4(uint32_t r[4], uint32_t addr) {
    asm volatile("ldmatrix.sync.aligned.m8n8.x4.shared.b16 {%0,%1,%2,%3}, [%4];"
                 : "=r"(r[0]), "=r"(r[1]), "=r"(r[2]), "=r"(r[3]) : "r"(addr));
}
__device__ __forceinline__ uint32_t swz(uint32_t r, uint32_t kc) {
    return r * 128 + ((kc ^ (r & 7)) << 4);
}

// ====== bf16 mma.sync GEMM core ======
template <int NT>
__device__ __forceinline__ void gemm_core(const bf16* __restrict__ A, int lda,
                                          const bf16* __restrict__ B, int ldb,
                                          float (&acc)[4][8][4]) {
    extern __shared__ char sh[];
    const uint32_t sbase = smem_u32(sh);
    const int tid = threadIdx.x, lane = tid & 31, wid = tid >> 5;
    const int wm = wid >> 1, wn = wid & 1;
    const int dl  = (lane & 7) + ((lane >> 3) & 1) * 8;
    const int dkc = lane >> 4;

    auto load_stage = [&](int s, int t) {
        uint32_t ab = sbase + s * STAGE_B;
        uint32_t bb = ab + TILE_B;
        const bf16* ga = A + t * BKC;
        const bf16* gb = B + t * BKC;
        #pragma unroll
        for (int it = 0; it < 8; it++) {
            int c = tid + it * 128;
            int r = c >> 3, kc = c & 7;
            uint32_t o = swz(r, kc);
            cpa16(ab + o, ga + (size_t)r * lda + kc * 8);
            cpa16(bb + o, gb + (size_t)r * ldb + kc * 8);
        }
        asm volatile("cp.async.commit_group;");
    };

    load_stage(0, 0);
    if (NT > 1) load_stage(1, 1);

    #pragma unroll 1
    for (int t = 0; t < NT; t++) {
        if (t + 1 < NT) asm volatile("cp.async.wait_group 1;");
        else            asm volatile("cp.async.wait_group 0;");
        __syncthreads();
        if (t + 2 < NT) load_stage((t + 2) % NSG, t + 2);

        uint32_t ab = sbase + (t % NSG) * STAGE_B;
        uint32_t bb = ab + TILE_B;
        #pragma unroll
        for (int ks = 0; ks < 4; ks++) {
            uint32_t a[4][4], b2[4][4];
            #pragma unroll
            for (int i = 0; i < 4; i++)
                ldmx4(a[i], ab + swz(wm * 64 + i * 16 + dl, ks * 2 + dkc));
            #pragma unroll
            for (int jj = 0; jj < 4; jj++)
                ldmx4(b2[jj], bb + swz(wn * 64 + jj * 16 + dl, ks * 2 + dkc));
            #pragma unroll
            for (int i = 0; i < 4; i++)
                #pragma unroll
                for (int j = 0; j < 8; j++)
                    mma_bf16(acc[i][j], a[i], b2[j >> 1][j & 1], b2[j >> 1][(j & 1) + 2]);
        }
    }
}

// ============ fused GroupNorm stats + normalize + transpose (half batch) ============
__global__ __launch_bounds__(256) void gnht(const float* __restrict__ x,
                                            const float* __restrict__ nw,
                                            const float* __restrict__ nb,
                                            int b0) {
    extern __shared__ char shraw[];
    bf16* sb = (bf16*)shraw;
    __shared__ float red_s[8], red_q[8], ssc[CPG], ssh[CPG];
    const int bg = blockIdx.x;
    const int b = b0 + bg / GROUPS, g = bg % GROUPS;
    const int tid = threadIdx.x;
    const float4* p4 = (const float4*)(x + ((size_t)b * CH + (size_t)g * CPG) * NPIX);

    float s = 0.f, sq = 0.f;
    #pragma unroll 4
    for (int i = 0; i < 32; i++) {
        int idx = tid + i * 256;
        float4 v = p4[idx];
        s += v.x + v.y + v.z + v.w;
        sq += v.x * v.x + v.y * v.y + v.z * v.z + v.w * v.w;
        int c = idx >> 8, n4 = idx & 255;
        uint32_t base = c * HT_STRIDE + n4 * 4;
        *(uint32_t*)&sb[base]     = pk2(v.x, v.y);
        *(uint32_t*)&sb[base + 2] = pk2(v.z, v.w);
    }
    #pragma unroll
    for (int o = 16; o; o >>= 1) {
        s  += __shfl_xor_sync(~0u, s, o);
        sq += __shfl_xor_sync(~0u, sq, o);
    }
    if ((tid & 31) == 0) { red_s[tid >> 5] = s; red_q[tid >> 5] = sq; }
    __syncthreads();
    if (tid < CPG) {
        float st = 0.f, qt = 0.f;
        #pragma unroll
        for (int i = 0; i < 8; i++) { st += red_s[i]; qt += red_q[i]; }
        const float inv_n = 1.f / (float)(CPG * NPIX);
        float mean = st * inv_n;
        float var  = qt * inv_n - mean * mean;
        float rstd = rsqrtf(var + EPSV);
        int c = g * CPG + tid;
        float sc = rstd * nw[c];
        ssc[tid] = sc;
        ssh[tid] = nb[c] - mean * sc;
    }
    __syncthreads();

    bf16* dst = g_hT + (size_t)b * NPIX * CH + g * CPG;
    const int cq = tid & 7, nb0 = tid >> 3;
    const float sc0 = ssc[cq * 4], sc1 = ssc[cq * 4 + 1], sc2 = ssc[cq * 4 + 2], sc3 = ssc[cq * 4 + 3];
    const float sh0 = ssh[cq * 4], sh1 = ssh[cq * 4 + 1], sh2 = ssh[cq * 4 + 2], sh3 = ssh[cq * 4 + 3];
    #pragma unroll 4
    for (int i = 0; i < 32; i++) {
        int n = nb0 + i * 32;
        float x0 = __bfloat162float(sb[(cq * 4 + 0) * HT_STRIDE + n]);
        float x1 = __bfloat162float(sb[(cq * 4 + 1) * HT_STRIDE + n]);
        float x2 = __bfloat162float(sb[(cq * 4 + 2) * HT_STRIDE + n]);
        float x3 = __bfloat162float(sb[(cq * 4 + 3) * HT_STRIDE + n]);
        uint2 w;
        w.x = pk2(fmaf(x0, sc0, sh0), fmaf(x1, sc1, sh1));
        w.y = pk2(fmaf(x2, sc2, sh2), fmaf(x3, sc3, sh3));
        *(uint2*)&dst[(size_t)n * CH + cq * 4] = w;
    }
}

// ================= weights -> bf16 (q rows pre-scaled log2e/16) =================
__global__ __launch_bounds__(256) void wcvt(const float* __restrict__ qkv_w,
                                            const float* __restrict__ proj_w) {
    int idx = blockIdx.x * 256 + threadIdx.x;
    #pragma unroll
    for (int u = 0; u < 4; u++) {
        int e = idx * 4 + u;
        if (e < 768 * CH) {
            int row = e / CH;
            float v = qkv_w[e];
            if (row < CH) v *= 0.0625f * 1.44269504f;
            if (row < 512) g_wqk[e] = __float2bfloat16(v);
            else           g_wv[e - 512 * CH] = __float2bfloat16(v);
        } else {
            int e2 = e - 768 * CH;
            g_wp[e2] = __float2bfloat16(proj_w[e2]);
        }
    }
}

// ========== merged QKV GEMM (half batch) ==========
__global__ __launch_bounds__(128, 2) void qkv_gemm(int b0) {
    const int b = b0 + blockIdx.z;
    const int wid = threadIdx.x >> 5, lane = threadIdx.x & 31, gr = lane >> 2, tg = lane & 3;
    const int wm = wid >> 1, wn = wid & 1;
    float acc[4][8][4] = {};

    if (blockIdx.y < 4) {
        const int m0 = blockIdx.x * 128;
        const int n0 = blockIdx.y * 128;
        gemm_core<CH / BKC>(g_hT + (size_t)b * NPIX * CH + (size_t)m0 * CH, CH,
                            g_wqk + (size_t)n0 * CH, CH, acc);
        bf16* dst = (n0 < 256 ? g_qT : g_kT) + (size_t)b * NPIX * CH;
        const int c0 = n0 & 255;
        #pragma unroll
        for (int i = 0; i < 4; i++) {
            int row = m0 + wm * 64 + i * 16 + gr;
            #pragma unroll
            for (int j = 0; j < 8; j++) {
                int col = c0 + wn * 64 + j * 8 + tg * 2;
                *(uint32_t*)&dst[(size_t)row * CH + col]       = pk2(acc[i][j][0], acc[i][j][1]);
                *(uint32_t*)&dst[(size_t)(row + 8) * CH + col] = pk2(acc[i][j][2], acc[i][j][3]);
            }
        }
    } else {
        const int m0 = (blockIdx.y - 4) * 128;
        const int n0 = blockIdx.x * 128;
        gemm_core<CH / BKC>(g_wv + (size_t)m0 * CH, CH,
                            g_hT + (size_t)b * NPIX * CH + (size_t)n0 * CH, CH, acc);
        bf16* dst = g_v + (size_t)b * CH * NPIX;
        #pragma unroll
        for (int i = 0; i < 4; i++) {
            int row = m0 + wm * 64 + i * 16 + gr;
            #pragma unroll
            for (int j = 0; j < 8; j++) {
                int col = n0 + wn * 64 + j * 8 + tg * 2;
                *(uint32_t*)&dst[(size_t)row * NPIX + col]       = pk2(acc[i][j][0], acc[i][j][1]);
                *(uint32_t*)&dst[(size_t)(row + 8) * NPIX + col] = pk2(acc[i][j][2], acc[i][j][3]);
            }
        }
    }
}

// ========== fused flash attention (half batch) ==========
__global__ __launch_bounds__(128, 2) void flash_attn(int b0) {
    extern __shared__ char sh[];
    const uint32_t sq = smem_u32(sh);
    const uint32_t sk = sq + 32768;
    const uint32_t sv = sq + 65536;
    const int b = b0 + blockIdx.y, nblk = blockIdx.x * 64;
    const int tid = threadIdx.x, lane = tid & 31, wid = tid >> 5;
    const int q0 = wid * 16;
    const int gr = lane >> 2, tg = lane & 3;
    const int dl = lane & 15, dkc = lane >> 4;

    const bf16* Qg = g_qT + (size_t)b * NPIX * CH + (size_t)nblk * CH;
    const bf16* Kg = g_kT + (size_t)b * NPIX * CH;
    const bf16* Vg = g_v  + (size_t)b * CH * NPIX;

    auto load_k = [&](int j) {
        #pragma unroll
        for (int it = 0; it < 16; it++) {
            int c = tid + it * 128;
            int p = c >> 9, rr = (c >> 3) & 63, kc = c & 7;
            cpa16(sk + p * 8192 + swz(rr, kc),
                  Kg + (size_t)(j * 64 + rr) * CH + p * 64 + kc * 8);
        }
        asm volatile("cp.async.commit_group;");
    };
    auto load_v = [&](int j) {
        #pragma unroll
        for (int it = 0; it < 16; it++) {
            int c = tid + it * 128;
            int rr = c >> 3, kc = c & 7;
            cpa16(sv + swz(rr, kc),
                  Vg + (size_t)rr * NPIX + j * 64 + kc * 8);
        }
        asm volatile("cp.async.commit_group;");
    };

    {
        #pragma unroll
        for (int it = 0; it < 16; it++) {
            int c = tid + it * 128;
            int p = c >> 9, rr = (c >> 3) & 63, kc = c & 7;
            cpa16(sq + p * 8192 + swz(rr, kc), Qg + (size_t)rr * CH + p * 64 + kc * 8);
            cpa16(sk + p * 8192 + swz(rr, kc), Kg + (size_t)rr * CH + p * 64 + kc * 8);
        }
        asm volatile("cp.async.commit_group;");
    }
    load_v(0);
    asm volatile("cp.async.wait_group 1;");
    __syncthreads();

    float oacc[32][4] = {};
    float m0 = -1e30f, m1 = -1e30f, l0 = 0.f, l1 = 0.f;

    #pragma unroll 1
    for (int j = 0; j < 16; j++) {
        float sacc[8][4];
        #pragma unroll
        for (int t = 0; t < 8; t++)
            sacc[t][0] = sacc[t][1] = sacc[t][2] = sacc[t][3] = 0.f;
        #pragma unroll
        for (int ks = 0; ks < 16; ks++) {
            uint32_t a[4];
            ldmx4(a, sq + (ks >> 2) * 8192 + swz(q0 + dl, ((ks & 3) << 1) + dkc));
            #pragma unroll
            for (int jj = 0; jj < 4; jj++) {
                uint32_t bb[4];
                ldmx4(bb, sk + (ks >> 2) * 8192 + swz(jj * 16 + dl, ((ks & 3) << 1) + dkc));
                mma_bf16(sacc[2 * jj],     a, bb[0], bb[2]);
                mma_bf16(sacc[2 * jj + 1], a, bb[1], bb[3]);
            }
        }
        float rx0 = -1e30f, rx1 = -1e30f;
        #pragma unroll
        for (int t = 0; t < 8; t++) {
            rx0 = fmaxf(rx0, fmaxf(sacc[t][0], sacc[t][1]));
            rx1 = fmaxf(rx1, fmaxf(sacc[t][2], sacc[t][3]));
        }
        rx0 = fmaxf(rx0, __shfl_xor_sync(~0u, rx0, 1)); rx0 = fmaxf(rx0, __shfl_xor_sync(~0u, rx0, 2));
        rx1 = fmaxf(rx1, __shfl_xor_sync(~0u, rx1, 1)); rx1 = fmaxf(rx1, __shfl_xor_sync(~0u, rx1, 2));
        float mn0 = fmaxf(m0, rx0), mn1 = fmaxf(m1, rx1);
        float al0 = exp2f(m0 - mn0), al1 = exp2f(m1 - mn1);
        m0 = mn0; m1 = mn1;
        float rs0 = 0.f, rs1 = 0.f;
        #pragma unroll
        for (int t = 0; t < 8; t++) {
            sacc[t][0] = exp2f(sacc[t][0] - mn0); rs0 += sacc[t][0];
            sacc[t][1] = exp2f(sacc[t][1] - mn0); rs0 += sacc[t][1];
            sacc[t][2] = exp2f(sacc[t][2] - mn1); rs1 += sacc[t][2];
            sacc[t][3] = exp2f(sacc[t][3] - mn1); rs1 += sacc[t][3];
        }
        l0 = l0 * al0 + rs0;
        l1 = l1 * al1 + rs1;
        if (al0 != 1.0f || al1 != 1.0f) {
            #pragma unroll
            for (int t = 0; t < 32; t++) {
                oacc[t][0] *= al0; oacc[t][1] *= al0;
                oacc[t][2] *= al1; oacc[t][3] *= al1;
            }
        }

        __syncthreads();
        if (j < 15) load_k(j + 1);
        if (j < 15) asm volatile("cp.async.wait_group 1;");
        else        asm volatile("cp.async.wait_group 0;");
        __syncthreads();

        #pragma unroll
        for (int kp = 0; kp < 4; kp++) {
            uint32_t a[4];
            a[0] = pk2(sacc[2 * kp][0],     sacc[2 * kp][1]);
            a[1] = pk2(sacc[2 * kp][2],     sacc[2 * kp][3]);
            a[2] = pk2(sacc[2 * kp + 1][0], sacc[2 * kp + 1][1]);
            a[3] = pk2(sacc[2 * kp + 1][2], sacc[2 * kp + 1][3]);
            #pragma unroll
            for (int cc = 0; cc < 16; cc++) {
                uint32_t bb[4];
                ldmx4(bb, sv + swz(cc * 16 + dl, kp * 2 + dkc));
                mma_bf16(oacc[2 * cc],     a, bb[0], bb[2]);
                mma_bf16(oacc[2 * cc + 1], a, bb[1], bb[3]);
            }
        }
        __syncthreads();
        if (j < 15) {
            load_v(j + 1);
            asm volatile("cp.async.wait_group 1;");
            __syncthreads();
        }
    }

    l0 += __shfl_xor_sync(~0u, l0, 1); l0 += __shfl_xor_sync(~0u, l0, 2);
    l1 += __shfl_xor_sync(~0u, l1, 1); l1 += __shfl_xor_sync(~0u, l1, 2);
    float inv0 = 1.f / l0, inv1 = 1.f / l1;
    bf16* dst = g_out + (size_t)b * NPIX * CH;
    int row0 = nblk + q0 + gr, row1 = row0 + 8;
    #pragma unroll
    for (int t = 0; t < 32; t++) {
        int col = t * 8 + tg * 2;
        *(uint32_t*)&dst[(size_t)row0 * CH + col] = pk2(oacc[t][0] * inv0, oacc[t][1] * inv0);
        *(uint32_t*)&dst[(size_t)row1 * CH + col] = pk2(oacc[t][2] * inv1, oacc[t][3] * inv1);
    }
}

// ========== proj (half batch) ==========
__global__ __launch_bounds__(128, 2) void proj_gemm(const float* __restrict__ x,
                                                    const float* __restrict__ pb,
                                                    float* __restrict__ y,
                                                    int b0) {
    const int b = b0 + blockIdx.z, m0 = blockIdx.y * 128, n0 = blockIdx.x * 128;
    float acc[4][8][4] = {};
    gemm_core<CH / BKC>(g_wp + (size_t)m0 * CH, CH,
                        g_out + (size_t)b * NPIX * CH + (size_t)n0 * CH, CH, acc);
    const int wid = threadIdx.x >> 5, lane = threadIdx.x & 31, gr = lane >> 2, tg = lane & 3;
    const int wm = wid >> 1, wn = wid & 1;
    const float* xb = x + (size_t)b * CH * NPIX;
    float* yb = y + (size_t)b * CH * NPIX;
    #pragma unroll
    for (int i = 0; i < 4; i++) {
        int row = m0 + wm * 64 + i * 16 + gr;
        float b0f = pb[row], b1f = pb[row + 8];
        #pragma unroll
        for (int j = 0; j < 8; j++) {
            int col = n0 + wn * 64 + j * 8 + tg * 2;
            size_t i0 = (size_t)row * NPIX + col;
            size_t i1 = (size_t)(row + 8) * NPIX + col;
            float2 x0 = *(const float2*)&xb[i0];
            float2 x1 = *(const float2*)&xb[i1];
            *(float2*)&yb[i0] = make_float2(x0.x + b0f + acc[i][j][0], x0.y + b0f + acc[i][j][1]);
            *(float2*)&yb[i1] = make_float2(x1.x + b1f + acc[i][j][2], x1.y + b1f + acc[i][j][3]);
        }
    }
}

extern "C" void kernel_launch(void* const* d_in, const int* in_sizes, int n_in,
                              void* d_out, int out_size) {
    const float* x      = (const float*)d_in[0];
    const float* norm_w = (const float*)d_in[1];
    const float* norm_b = (const float*)d_in[2];
    const float* qkv_w  = (const float*)d_in[3];
    const float* proj_w = (const float*)d_in[4];
    const float* proj_b = (const float*)d_in[5];
    float* y = (float*)d_out;

    static bool init = false;
    static cudaStream_t s2;
    static cudaEvent_t eRoot, eWcvt, eJoin;
    if (!init) {
        cudaStreamCreateWithFlags(&s2, cudaStreamNonBlocking);
        cudaEventCreateWithFlags(&eRoot, cudaEventDisableTiming);
        cudaEventCreateWithFlags(&eWcvt, cudaEventDisableTiming);
        cudaEventCreateWithFlags(&eJoin, cudaEventDisableTiming);
        cudaFuncSetAttribute(gnht,       cudaFuncAttributeMaxDynamicSharedMemorySize, GNHT_SMEM);
        cudaFuncSetAttribute(qkv_gemm,   cudaFuncAttributeMaxDynamicSharedMemorySize, SMEM_REQ);
        cudaFuncSetAttribute(proj_gemm,  cudaFuncAttributeMaxDynamicSharedMemorySize, SMEM_REQ);
        cudaFuncSetAttribute(flash_attn, cudaFuncAttributeMaxDynamicSharedMemorySize, FA_SMEM);
        init = true;
    }

    // Detect the stream being captured (harness may use legacy or per-thread default).
    cudaStream_t sO = cudaStreamLegacy;
    {
        cudaStreamCaptureStatus st = cudaStreamCaptureStatusNone;
        if (cudaStreamIsCapturing(cudaStreamPerThread, &st) == cudaSuccess &&
            st == cudaStreamCaptureStatusActive) {
            sO = cudaStreamPerThread;
        } else {
            cudaStreamCaptureStatus st2 = cudaStreamCaptureStatusNone;
            cudaStreamIsCapturing(cudaStreamLegacy, &st2);
            sO = cudaStreamLegacy;   // works both for legacy-capture and non-capture runs
        }
    }

    // fork: s2 branch handles wcvt + batches 16..31
    cudaEventRecord(eRoot, sO);
    cudaStreamWaitEvent(s2, eRoot, 0);

    // branch B (s2): weights first (needed by both), then its half-pipeline
    wcvt<<<256, 256, 0, s2>>>(qkv_w, proj_w);
    cudaEventRecord(eWcvt, s2);
    gnht<<<HBATCH * GROUPS, 256, GNHT_SMEM, s2>>>(x, norm_w, norm_b, HBATCH);
    qkv_gemm<<<dim3(NPIX / 128, 6, HBATCH), 128, SMEM_REQ, s2>>>(HBATCH);
    flash_attn<<<dim3(NPIX / 64, HBATCH), 128, FA_SMEM, s2>>>(HBATCH);
    proj_gemm<<<dim3(NPIX / 128, 2, HBATCH), 128, SMEM_REQ, s2>>>(x, proj_b, y, HBATCH);

    // branch A (sO): batches 0..15 (waits for weights from branch B)
    gnht<<<HBATCH * GROUPS, 256, GNHT_SMEM, sO>>>(x, norm_w, norm_b, 0);
    cudaStreamWaitEvent(sO, eWcvt, 0);
    qkv_gemm<<<dim3(NPIX / 128, 6, HBATCH), 128, SMEM_REQ, sO>>>(0);
    flash_attn<<<dim3(NPIX / 64, HBATCH), 128, FA_SMEM, sO>>>(0);
    proj_gemm<<<dim3(NPIX / 128, 2, HBATCH), 128, SMEM_REQ, sO>>>(x, proj_b, y, 0);

    // join
    cudaEventRecord(eJoin, s2);
    cudaStreamWaitEvent(sO, eJoin, 0);
}

// round 14
// speedup vs baseline: 1.1207x; 1.0091x over previous
#include <cuda_runtime.h>
#include <cuda_bf16.h>
#include <stdint.h>

#define BATCH 32
#define QB 8                          // batches per branch
#define CH    256
#define NPIX  1024
#define GROUPS 8
#define CPG   32
#define EPSV  1e-5f

#define BKC 64
#define TILE_B  16384
#define STAGE_B (2 * TILE_B)
#define NSG 3
#define SMEM_REQ (NSG * STAGE_B)     // 98304 for gemm kernels
#define FA_SMEM 98304                // 96KB: Q 32K + K 32K + V 32K -> 2 CTAs/SM
#define HT_STRIDE 1042
#define GNHT_SMEM (CPG * HT_STRIDE * 2)

typedef __nv_bfloat16 bf16;

// ---- scratch ----
__device__ bf16 g_hT [(size_t)BATCH * NPIX * CH];
__device__ bf16 g_qT [(size_t)BATCH * NPIX * CH];    // [b][n][c] (W_q pre-scaled log2e/16)
__device__ bf16 g_kT [(size_t)BATCH * NPIX * CH];    // [b][m][c]
__device__ bf16 g_v  [(size_t)BATCH * CH * NPIX];    // [b][c][m]
__device__ bf16 g_out[(size_t)BATCH * NPIX * CH];    // [b][n][c]
__device__ bf16 g_wqk[(size_t)512 * CH];
__device__ bf16 g_wv [(size_t)CH * CH];
__device__ bf16 g_wp [(size_t)CH * CH];

// ================= helpers =================
__device__ __forceinline__ uint32_t smem_u32(const void* p) {
    uint32_t a;
    asm("{ .reg .u64 t; cvta.to.shared.u64 t, %1; cvt.u32.u64 %0, t; }" : "=r"(a) : "l"(p));
    return a;
}
__device__ __forceinline__ void cpa16(uint32_t d, const void* s) {
    asm volatile("cp.async.cg.shared.global [%0], [%1], 16;" :: "r"(d), "l"(s));
}
__device__ __forceinline__ uint32_t pk2(float lo, float hi) {
    uint32_t r;
    asm("cvt.rn.bf16x2.f32 %0, %1, %2;" : "=r"(r) : "f"(hi), "f"(lo));
    return r;
}
__device__ __forceinline__ void mma_bf16(float c[4], const uint32_t a[4], uint32_t b0, uint32_t b1) {
    asm volatile("mma.sync.aligned.m16n8k16.row.col.f32.bf16.bf16.f32 "
                 "{%0,%1,%2,%3}, {%4,%5,%6,%7}, {%8,%9}, {%0,%1,%2,%3};\n"
                 : "+f"(c[0]), "+f"(c[1]), "+f"(c[2]), "+f"(c[3])
                 : "r"(a[0]), "r"(a[1]), "r"(a[2]), "r"(a[3]), "r"(b0), "r"(b1));
}
__device__ __forceinline__ void ldmx4(uint32_t r[4], uint32_t addr) {
    asm volatile("ldmatrix.sync.aligned.m8n8.x4.shared.b16 {%0,%1,%2,%3}, [%4];"
                 : "=r"(r[0]), "=r"(r[1]), "=r"(r[2]), "=r"(r[3]) : "r"(addr));
}
__device__ __forceinline__ uint32_t swz(uint32_t r, uint32_t kc) {
    return r * 128 + ((kc ^ (r & 7)) << 4);
}

// ====== bf16 mma.sync GEMM core ======
template <int NT>
__device__ __forceinline__ void gemm_core(const bf16* __restrict__ A, int lda,
                                          const bf16* __restrict__ B, int ldb,
                                          float (&acc)[4][8][4]) {
    extern __shared__ char sh[];
    const uint32_t sbase = smem_u32(sh);
    const int tid = threadIdx.x, lane = tid & 31, wid = tid >> 5;
    const int wm = wid >> 1, wn = wid & 1;
    const int dl  = (lane & 7) + ((lane >> 3) & 1) * 8;
    const int dkc = lane >> 4;

    auto load_stage = [&](int s, int t) {
        uint32_t ab = sbase + s * STAGE_B;
        uint32_t bb = ab + TILE_B;
        const bf16* ga = A + t * BKC;
        const bf16* gb = B + t * BKC;
        #pragma unroll
        for (int it = 0; it < 8; it++) {
            int c = tid + it * 128;
            int r = c >> 3, kc = c & 7;
            uint32_t o = swz(r, kc);
            cpa16(ab + o, ga + (size_t)r * lda + kc * 8);
            cpa16(bb + o, gb + (size_t)r * ldb + kc * 8);
        }
        asm volatile("cp.async.commit_group;");
    };

    load_stage(0, 0);
    if (NT > 1) load_stage(1, 1);

    #pragma unroll 1
    for (int t = 0; t < NT; t++) {
        if (t + 1 < NT) asm volatile("cp.async.wait_group 1;");
        else            asm volatile("cp.async.wait_group 0;");
        __syncthreads();
        if (t + 2 < NT) load_stage((t + 2) % NSG, t + 2);

        uint32_t ab = sbase + (t % NSG) * STAGE_B;
        uint32_t bb = ab + TILE_B;
        #pragma unroll
        for (int ks = 0; ks < 4; ks++) {
            uint32_t a[4][4], b2[4][4];
            #pragma unroll
            for (int i = 0; i < 4; i++)
                ldmx4(a[i], ab + swz(wm * 64 + i * 16 + dl, ks * 2 + dkc));
            #pragma unroll
            for (int jj = 0; jj < 4; jj++)
                ldmx4(b2[jj], bb + swz(wn * 64 + jj * 16 + dl, ks * 2 + dkc));
            #pragma unroll
            for (int i = 0; i < 4; i++)
                #pragma unroll
                for (int j = 0; j < 8; j++)
                    mma_bf16(acc[i][j], a[i], b2[j >> 1][j & 1], b2[j >> 1][(j & 1) + 2]);
        }
    }
}

// ============ fused GroupNorm stats + normalize + transpose (branch) ============
__global__ __launch_bounds__(256) void gnht(const float* __restrict__ x,
                                            const float* __restrict__ nw,
                                            const float* __restrict__ nb,
                                            int b0) {
    extern __shared__ char shraw[];
    bf16* sb = (bf16*)shraw;
    __shared__ float red_s[8], red_q[8], ssc[CPG], ssh[CPG];
    const int bg = blockIdx.x;
    const int b = b0 + bg / GROUPS, g = bg % GROUPS;
    const int tid = threadIdx.x;
    const float4* p4 = (const float4*)(x + ((size_t)b * CH + (size_t)g * CPG) * NPIX);

    float s = 0.f, sq = 0.f;
    #pragma unroll 4
    for (int i = 0; i < 32; i++) {
        int idx = tid + i * 256;
        float4 v = p4[idx];
        s += v.x + v.y + v.z + v.w;
        sq += v.x * v.x + v.y * v.y + v.z * v.z + v.w * v.w;
        int c = idx >> 8, n4 = idx & 255;
        uint32_t base = c * HT_STRIDE + n4 * 4;
        *(uint32_t*)&sb[base]     = pk2(v.x, v.y);
        *(uint32_t*)&sb[base + 2] = pk2(v.z, v.w);
    }
    #pragma unroll
    for (int o = 16; o; o >>= 1) {
        s  += __shfl_xor_sync(~0u, s, o);
        sq += __shfl_xor_sync(~0u, sq, o);
    }
    if ((tid & 31) == 0) { red_s[tid >> 5] = s; red_q[tid >> 5] = sq; }
    __syncthreads();
    if (tid < CPG) {
        float st = 0.f, qt = 0.f;
        #pragma unroll
        for (int i = 0; i < 8; i++) { st += red_s[i]; qt += red_q[i]; }
        const float inv_n = 1.f / (float)(CPG * NPIX);
        float mean = st * inv_n;
        float var  = qt * inv_n - mean * mean;
        float rstd = rsqrtf(var + EPSV);
        int c = g * CPG + tid;
        float sc = rstd * nw[c];
        ssc[tid] = sc;
        ssh[tid] = nb[c] - mean * sc;
    }
    __syncthreads();

    bf16* dst = g_hT + (size_t)b * NPIX * CH + g * CPG;
    const int cq = tid & 7, nb0 = tid >> 3;
    const float sc0 = ssc[cq * 4], sc1 = ssc[cq * 4 + 1], sc2 = ssc[cq * 4 + 2], sc3 = ssc[cq * 4 + 3];
    const float sh0 = ssh[cq * 4], sh1 = ssh[cq * 4 + 1], sh2 = ssh[cq * 4 + 2], sh3 = ssh[cq * 4 + 3];
    #pragma unroll 4
    for (int i = 0; i < 32; i++) {
        int n = nb0 + i * 32;
        float x0 = __bfloat162float(sb[(cq * 4 + 0) * HT_STRIDE + n]);
        float x1 = __bfloat162float(sb[(cq * 4 + 1) * HT_STRIDE + n]);
        float x2 = __bfloat162float(sb[(cq * 4 + 2) * HT_STRIDE + n]);
        float x3 = __bfloat162float(sb[(cq * 4 + 3) * HT_STRIDE + n]);
        uint2 w;
        w.x = pk2(fmaf(x0, sc0, sh0), fmaf(x1, sc1, sh1));
        w.y = pk2(fmaf(x2, sc2, sh2), fmaf(x3, sc3, sh3));
        *(uint2*)&dst[(size_t)n * CH + cq * 4] = w;
    }
}

// ================= weights -> bf16 (q rows pre-scaled log2e/16) =================
__global__ __launch_bounds__(256) void wcvt(const float* __restrict__ qkv_w,
                                            const float* __restrict__ proj_w) {
    int idx = blockIdx.x * 256 + threadIdx.x;
    #pragma unroll
    for (int u = 0; u < 4; u++) {
        int e = idx * 4 + u;
        if (e < 768 * CH) {
            int row = e / CH;
            float v = qkv_w[e];
            if (row < CH) v *= 0.0625f * 1.44269504f;
            if (row < 512) g_wqk[e] = __float2bfloat16(v);
            else           g_wv[e - 512 * CH] = __float2bfloat16(v);
        } else {
            int e2 = e - 768 * CH;
            g_wp[e2] = __float2bfloat16(proj_w[e2]);
        }
    }
}

// ========== merged QKV GEMM (branch) ==========
__global__ __launch_bounds__(128, 2) void qkv_gemm(int b0) {
    const int b = b0 + blockIdx.z;
    const int wid = threadIdx.x >> 5, lane = threadIdx.x & 31, gr = lane >> 2, tg = lane & 3;
    const int wm = wid >> 1, wn = wid & 1;
    float acc[4][8][4] = {};

    if (blockIdx.y < 4) {
        const int m0 = blockIdx.x * 128;
        const int n0 = blockIdx.y * 128;
        gemm_core<CH / BKC>(g_hT + (size_t)b * NPIX * CH + (size_t)m0 * CH, CH,
                            g_wqk + (size_t)n0 * CH, CH, acc);
        bf16* dst = (n0 < 256 ? g_qT : g_kT) + (size_t)b * NPIX * CH;
        const int c0 = n0 & 255;
        #pragma unroll
        for (int i = 0; i < 4; i++) {
            int row = m0 + wm * 64 + i * 16 + gr;
            #pragma unroll
            for (int j = 0; j < 8; j++) {
                int col = c0 + wn * 64 + j * 8 + tg * 2;
                *(uint32_t*)&dst[(size_t)row * CH + col]       = pk2(acc[i][j][0], acc[i][j][1]);
                *(uint32_t*)&dst[(size_t)(row + 8) * CH + col] = pk2(acc[i][j][2], acc[i][j][3]);
            }
        }
    } else {
        const int m0 = (blockIdx.y - 4) * 128;
        const int n0 = blockIdx.x * 128;
        gemm_core<CH / BKC>(g_wv + (size_t)m0 * CH, CH,
                            g_hT + (size_t)b * NPIX * CH + (size_t)n0 * CH, CH, acc);
        bf16* dst = g_v + (size_t)b * CH * NPIX;
        #pragma unroll
        for (int i = 0; i < 4; i++) {
            int row = m0 + wm * 64 + i * 16 + gr;
            #pragma unroll
            for (int j = 0; j < 8; j++) {
                int col = n0 + wn * 64 + j * 8 + tg * 2;
                *(uint32_t*)&dst[(size_t)row * NPIX + col]       = pk2(acc[i][j][0], acc[i][j][1]);
                *(uint32_t*)&dst[(size_t)(row + 8) * NPIX + col] = pk2(acc[i][j][2], acc[i][j][3]);
            }
        }
    }
}

// ========== fused flash attention (branch) ==========
__global__ __launch_bounds__(128, 2) void flash_attn(int b0) {
    extern __shared__ char sh[];
    const uint32_t sq = smem_u32(sh);
    const uint32_t sk = sq + 32768;
    const uint32_t sv = sq + 65536;
    const int b = b0 + blockIdx.y, nblk = blockIdx.x * 64;
    const int tid = threadIdx.x, lane = tid & 31, wid = tid >> 5;
    const int q0 = wid * 16;
    const int gr = lane >> 2, tg = lane & 3;
    const int dl = lane & 15, dkc = lane >> 4;

    const bf16* Qg = g_qT + (size_t)b * NPIX * CH + (size_t)nblk * CH;
    const bf16* Kg = g_kT + (size_t)b * NPIX * CH;
    const bf16* Vg = g_v  + (size_t)b * CH * NPIX;

    auto load_k = [&](int j) {
        #pragma unroll
        for (int it = 0; it < 16; it++) {
            int c = tid + it * 128;
            int p = c >> 9, rr = (c >> 3) & 63, kc = c & 7;
            cpa16(sk + p * 8192 + swz(rr, kc),
                  Kg + (size_t)(j * 64 + rr) * CH + p * 64 + kc * 8);
        }
        asm volatile("cp.async.commit_group;");
    };
    auto load_v = [&](int j) {
        #pragma unroll
        for (int it = 0; it < 16; it++) {
            int c = tid + it * 128;
            int rr = c >> 3, kc = c & 7;
            cpa16(sv + swz(rr, kc),
                  Vg + (size_t)rr * NPIX + j * 64 + kc * 8);
        }
        asm volatile("cp.async.commit_group;");
    };

    {
        #pragma unroll
        for (int it = 0; it < 16; it++) {
            int c = tid + it * 128;
            int p = c >> 9, rr = (c >> 3) & 63, kc = c & 7;
            cpa16(sq + p * 8192 + swz(rr, kc), Qg + (size_t)rr * CH + p * 64 + kc * 8);
            cpa16(sk + p * 8192 + swz(rr, kc), Kg + (size_t)rr * CH + p * 64 + kc * 8);
        }
        asm volatile("cp.async.commit_group;");
    }
    load_v(0);
    asm volatile("cp.async.wait_group 1;");
    __syncthreads();

    float oacc[32][4] = {};
    float m0 = -1e30f, m1 = -1e30f, l0 = 0.f, l1 = 0.f;

    #pragma unroll 1
    for (int j = 0; j < 16; j++) {
        float sacc[8][4];
        #pragma unroll
        for (int t = 0; t < 8; t++)
            sacc[t][0] = sacc[t][1] = sacc[t][2] = sacc[t][3] = 0.f;
        #pragma unroll
        for (int ks = 0; ks < 16; ks++) {
            uint32_t a[4];
            ldmx4(a, sq + (ks >> 2) * 8192 + swz(q0 + dl, ((ks & 3) << 1) + dkc));
            #pragma unroll
            for (int jj = 0; jj < 4; jj++) {
                uint32_t bb[4];
                ldmx4(bb, sk + (ks >> 2) * 8192 + swz(jj * 16 + dl, ((ks & 3) << 1) + dkc));
                mma_bf16(sacc[2 * jj],     a, bb[0], bb[2]);
                mma_bf16(sacc[2 * jj + 1], a, bb[1], bb[3]);
            }
        }
        float rx0 = -1e30f, rx1 = -1e30f;
        #pragma unroll
        for (int t = 0; t < 8; t++) {
            rx0 = fmaxf(rx0, fmaxf(sacc[t][0], sacc[t][1]));
            rx1 = fmaxf(rx1, fmaxf(sacc[t][2], sacc[t][3]));
        }
        rx0 = fmaxf(rx0, __shfl_xor_sync(~0u, rx0, 1)); rx0 = fmaxf(rx0, __shfl_xor_sync(~0u, rx0, 2));
        rx1 = fmaxf(rx1, __shfl_xor_sync(~0u, rx1, 1)); rx1 = fmaxf(rx1, __shfl_xor_sync(~0u, rx1, 2));
        float mn0 = fmaxf(m0, rx0), mn1 = fmaxf(m1, rx1);
        float al0 = exp2f(m0 - mn0), al1 = exp2f(m1 - mn1);
        m0 = mn0; m1 = mn1;
        float rs0 = 0.f, rs1 = 0.f;
        #pragma unroll
        for (int t = 0; t < 8; t++) {
            sacc[t][0] = exp2f(sacc[t][0] - mn0); rs0 += sacc[t][0];
            sacc[t][1] = exp2f(sacc[t][1] - mn0); rs0 += sacc[t][1];
            sacc[t][2] = exp2f(sacc[t][2] - mn1); rs1 += sacc[t][2];
            sacc[t][3] = exp2f(sacc[t][3] - mn1); rs1 += sacc[t][3];
        }
        l0 = l0 * al0 + rs0;
        l1 = l1 * al1 + rs1;
        if (al0 != 1.0f || al1 != 1.0f) {
            #pragma unroll
            for (int t = 0; t < 32; t++) {
                oacc[t][0] *= al0; oacc[t][1] *= al0;
                oacc[t][2] *= al1; oacc[t][3] *= al1;
            }
        }

        __syncthreads();
        if (j < 15) load_k(j + 1);
        if (j < 15) asm volatile("cp.async.wait_group 1;");
        else        asm volatile("cp.async.wait_group 0;");
        __syncthreads();

        #pragma unroll
        for (int kp = 0; kp < 4; kp++) {
            uint32_t a[4];
            a[0] = pk2(sacc[2 * kp][0],     sacc[2 * kp][1]);
            a[1] = pk2(sacc[2 * kp][2],     sacc[2 * kp][3]);
            a[2] = pk2(sacc[2 * kp + 1][0], sacc[2 * kp + 1][1]);
            a[3] = pk2(sacc[2 * kp + 1][2], sacc[2 * kp + 1][3]);
            #pragma unroll
            for (int cc = 0; cc < 16; cc++) {
                uint32_t bb[4];
                ldmx4(bb, sv + swz(cc * 16 + dl, kp * 2 + dkc));
                mma_bf16(oacc[2 * cc],     a, bb[0], bb[2]);
                mma_bf16(oacc[2 * cc + 1], a, bb[1], bb[3]);
            }
        }
        __syncthreads();
        if (j < 15) {
            load_v(j + 1);
            asm volatile("cp.async.wait_group 1;");
            __syncthreads();
        }
    }

    l0 += __shfl_xor_sync(~0u, l0, 1); l0 += __shfl_xor_sync(~0u, l0, 2);
    l1 += __shfl_xor_sync(~0u, l1, 1); l1 += __shfl_xor_sync(~0u, l1, 2);
    float inv0 = 1.f / l0, inv1 = 1.f / l1;
    bf16* dst = g_out + (size_t)b * NPIX * CH;
    int row0 = nblk + q0 + gr, row1 = row0 + 8;
    #pragma unroll
    for (int t = 0; t < 32; t++) {
        int col = t * 8 + tg * 2;
        *(uint32_t*)&dst[(size_t)row0 * CH + col] = pk2(oacc[t][0] * inv0, oacc[t][1] * inv0);
        *(uint32_t*)&dst[(size_t)row1 * CH + col] = pk2(oacc[t][2] * inv1, oacc[t][3] * inv1);
    }
}

// ========== proj (branch) ==========
__global__ __launch_bounds__(128, 2) void proj_gemm(const float* __restrict__ x,
                                                    const float* __restrict__ pb,
                                                    float* __restrict__ y,
                                                    int b0) {
    const int b = b0 + blockIdx.z, m0 = blockIdx.y * 128, n0 = blockIdx.x * 128;
    float acc[4][8][4] = {};
    gemm_core<CH / BKC>(g_wp + (size_t)m0 * CH, CH,
                        g_out + (size_t)b * NPIX * CH + (size_t)n0 * CH, CH, acc);
    const int wid = threadIdx.x >> 5, lane = threadIdx.x & 31, gr = lane >> 2, tg = lane & 3;
    const int wm = wid >> 1, wn = wid & 1;
    const float* xb = x + (size_t)b * CH * NPIX;
    float* yb = y + (size_t)b * CH * NPIX;
    #pragma unroll
    for (int i = 0; i < 4; i++) {
        int row = m0 + wm * 64 + i * 16 + gr;
        float b0f = pb[row], b1f = pb[row + 8];
        #pragma unroll
        for (int j = 0; j < 8; j++) {
            int col = n0 + wn * 64 + j * 8 + tg * 2;
            size_t i0 = (size_t)row * NPIX + col;
            size_t i1 = (size_t)(row + 8) * NPIX + col;
            float2 x0 = *(const float2*)&xb[i0];
            float2 x1 = *(const float2*)&xb[i1];
            *(float2*)&yb[i0] = make_float2(x0.x + b0f + acc[i][j][0], x0.y + b0f + acc[i][j][1]);
            *(float2*)&yb[i1] = make_float2(x1.x + b1f + acc[i][j][2], x1.y + b1f + acc[i][j][3]);
        }
    }
}

extern "C" void kernel_launch(void* const* d_in, const int* in_sizes, int n_in,
                              void* d_out, int out_size) {
    const float* x      = (const float*)d_in[0];
    const float* norm_w = (const float*)d_in[1];
    const float* norm_b = (const float*)d_in[2];
    const float* qkv_w  = (const float*)d_in[3];
    const float* proj_w = (const float*)d_in[4];
    const float* proj_b = (const float*)d_in[5];
    float* y = (float*)d_out;

    static bool init = false;
    static cudaStream_t sx[3];
    static cudaEvent_t eRoot, eWcvt, eJoin[3];
    if (!init) {
        for (int i = 0; i < 3; i++) {
            cudaStreamCreateWithFlags(&sx[i], cudaStreamNonBlocking);
            cudaEventCreateWithFlags(&eJoin[i], cudaEventDisableTiming);
        }
        cudaEventCreateWithFlags(&eRoot, cudaEventDisableTiming);
        cudaEventCreateWithFlags(&eWcvt, cudaEventDisableTiming);
        cudaFuncSetAttribute(gnht,       cudaFuncAttributeMaxDynamicSharedMemorySize, GNHT_SMEM);
        cudaFuncSetAttribute(qkv_gemm,   cudaFuncAttributeMaxDynamicSharedMemorySize, SMEM_REQ);
        cudaFuncSetAttribute(proj_gemm,  cudaFuncAttributeMaxDynamicSharedMemorySize, SMEM_REQ);
        cudaFuncSetAttribute(flash_attn, cudaFuncAttributeMaxDynamicSharedMemorySize, FA_SMEM);
        init = true;
    }

    // Detect the stream being captured (legacy or per-thread default).
    cudaStream_t sO = cudaStreamLegacy;
    {
        cudaStreamCaptureStatus st = cudaStreamCaptureStatusNone;
        if (cudaStreamIsCapturing(cudaStreamPerThread, &st) == cudaSuccess &&
            st == cudaStreamCaptureStatusActive) {
            sO = cudaStreamPerThread;
        }
    }

    // fork
    cudaEventRecord(eRoot, sO);
    for (int i = 0; i < 3; i++) cudaStreamWaitEvent(sx[i], eRoot, 0);

    // origin branch: weights first (gates every qkv), then batches 0..7
    wcvt<<<256, 256, 0, sO>>>(qkv_w, proj_w);
    cudaEventRecord(eWcvt, sO);
    gnht<<<QB * GROUPS, 256, GNHT_SMEM, sO>>>(x, norm_w, norm_b, 0);
    qkv_gemm<<<dim3(NPIX / 128, 6, QB), 128, SMEM_REQ, sO>>>(0);
    flash_attn<<<dim3(NPIX / 64, QB), 128, FA_SMEM, sO>>>(0);
    proj_gemm<<<dim3(NPIX / 128, 2, QB), 128, SMEM_REQ, sO>>>(x, proj_b, y, 0);

    // side branches: batches 8..15 / 16..23 / 24..31
    for (int i = 0; i < 3; i++) {
        int b0 = (i + 1) * QB;
        gnht<<<QB * GROUPS, 256, GNHT_SMEM, sx[i]>>>(x, norm_w, norm_b, b0);
        cudaStreamWaitEvent(sx[i], eWcvt, 0);
        qkv_gemm<<<dim3(NPIX / 128, 6, QB), 128, SMEM_REQ, sx[i]>>>(b0);
        flash_attn<<<dim3(NPIX / 64, QB), 128, FA_SMEM, sx[i]>>>(b0);
        proj_gemm<<<dim3(NPIX / 128, 2, QB), 128, SMEM_REQ, sx[i]>>>(x, proj_b, y, b0);
        cudaEventRecord(eJoin[i], sx[i]);
    }

    // join
    for (int i = 0; i < 3; i++) cudaStreamWaitEvent(sO, eJoin[i], 0);
}